// round 4
// baseline (speedup 1.0000x reference)
#include <cuda_runtime.h>
#include <math.h>
#include <float.h>

#define BB 4
#define NP0 4096
#define NEWP 1152
#define MAXN (NP0 + 10*NEWP)     // 15616
#define GD 256
#define HD 128
#define KSEL 64
#define NSTEPS 10
#define REFO (NEWP*3)            // 3456

// ---------------- device scratch (static: no allocation) ----------------
__device__ float    g_canvas[BB][MAXN][3];
__device__ float    g_F2T[128][BB*MAXN];      // encoder layer-2 activations, transposed
__device__ unsigned g_gfenc[BB][GD];
__device__ float    g_h[BB][HD];
__device__ float    g_c[BB][HD];
__device__ float    g_scores[BB][MAXN];
__device__ float    g_center[BB][3];
__device__ float    g_patch[BB][3];
__device__ float    g_hid[BB][HD];
__device__ float    g_attpart[8][BB][128];    // partial bias sums
__device__ double   g_acc[4];

// monotone float<->uint encoding (for atomicMax over signed floats)
__device__ __forceinline__ unsigned fenc(float f){
    unsigned u = __float_as_uint(f);
    return (u & 0x80000000u) ? ~u : (u | 0x80000000u);
}
__device__ __forceinline__ float fdec(unsigned e){
    unsigned u = (e & 0x80000000u) ? (e & 0x7fffffffu) : ~e;
    return __uint_as_float(u);
}

// ---------------- init ----------------
__global__ void k_init(const float* __restrict__ points){
    int i = blockIdx.x*blockDim.x + threadIdx.x;
    if(i < BB*NP0*3){
        int b = i/(NP0*3); int r = i - b*(NP0*3);
        g_canvas[b][r/3][r%3] = points[i];
    }
    if(i < BB*HD){ g_h[i/HD][i%HD] = 0.f; g_c[i/HD][i%HD] = 0.f; }
    if(i < 4) g_acc[i] = 0.0;
}

// ---------------- encoder layers 1-2 (per point), fused gfeat re-init ----------------
__global__ void k_enc12(const float* __restrict__ w1, const float* __restrict__ b1,
                        const float* __restrict__ w2, const float* __restrict__ b2, int N){
    __shared__ float s_w1[192];
    __shared__ float s_b1[64];
    __shared__ float s_w2[64*128];
    __shared__ float s_b2[128];
    int tid = threadIdx.x;
    if(blockIdx.x == 0){  // re-init gfeat max accumulators for this step
        for(int i=tid;i<BB*GD;i+=256) ((unsigned*)g_gfenc)[i] = fenc(-FLT_MAX);
    }
    for(int i=tid;i<192;i+=256) s_w1[i]=w1[i];
    if(tid<64)  s_b1[tid]=b1[tid];
    if(tid<128) s_b2[tid]=b2[tid];
    for(int i=tid;i<8192;i+=256) s_w2[i]=w2[i];
    __syncthreads();

    int p = blockIdx.x*256 + tid;
    if(p >= BB*N) return;
    int b = p / N, n = p - b*N;
    float x = g_canvas[b][n][0], y = g_canvas[b][n][1], z = g_canvas[b][n][2];

    float f1[64];
    #pragma unroll
    for(int o=0;o<64;o++)
        f1[o] = fmaxf(0.f, s_b1[o] + x*s_w1[o] + y*s_w1[64+o] + z*s_w1[128+o]);

    size_t col = (size_t)b*MAXN + n;
    for(int j=0;j<128;j+=4){
        float a0=s_b2[j], a1=s_b2[j+1], a2=s_b2[j+2], a3=s_b2[j+3];
        #pragma unroll
        for(int k=0;k<64;k++){
            float4 w = *(const float4*)&s_w2[k*128 + j];
            float f = f1[k];
            a0 += f*w.x; a1 += f*w.y; a2 += f*w.z; a3 += f*w.w;
        }
        g_F2T[j  ][col] = fmaxf(a0,0.f);
        g_F2T[j+1][col] = fmaxf(a1,0.f);
        g_F2T[j+2][col] = fmaxf(a2,0.f);
        g_F2T[j+3][col] = fmaxf(a3,0.f);
    }
}

// ---------------- encoder layer 3 GEMM + channel max (gfeat) ----------------
// grid (BB, N/64), block 512.  Tile: 64 points x 256 channels, K=128.
// One shared tile load serves all 256 channels; 32 accs/thread -> <=63 regs, 50% occ.
__global__ void __launch_bounds__(512,2)
k_enc3(const float* __restrict__ w3, const float* __restrict__ b3){
    __shared__ float sF[128*64];   // [k][p]
    int b = blockIdx.x;
    int pbase = blockIdx.y*64;
    int tid = threadIdx.x;
    size_t base = (size_t)b*MAXN + pbase;
    for(int i=tid;i<128*64;i+=512){
        int k = i>>6, p = i&63;
        sF[i] = g_F2T[k][base + p];
    }
    __syncthreads();

    int chb = (tid & 31) * 8;   // 8 consecutive channels
    int pg  = tid >> 5;         // point group 0..15 (4 points each)
    float acc[4][8];
    #pragma unroll
    for(int i=0;i<4;i++)
        #pragma unroll
        for(int j=0;j<8;j++) acc[i][j]=0.f;

    const float* w3p = w3 + chb;
    #pragma unroll 4
    for(int k=0;k<128;k++){
        float4 wa = *(const float4*)(w3p + (size_t)k*256);
        float4 wb = *(const float4*)(w3p + (size_t)k*256 + 4);
        float4 f  = *(const float4*)&sF[k*64 + pg*4];
        float ff[4] = {f.x, f.y, f.z, f.w};
        #pragma unroll
        for(int i=0;i<4;i++){
            float fv = ff[i];
            acc[i][0]+=fv*wa.x; acc[i][1]+=fv*wa.y; acc[i][2]+=fv*wa.z; acc[i][3]+=fv*wa.w;
            acc[i][4]+=fv*wb.x; acc[i][5]+=fv*wb.y; acc[i][6]+=fv*wb.z; acc[i][7]+=fv*wb.w;
        }
    }
    float m[8];
    #pragma unroll
    for(int j=0;j<8;j++){
        float mm = fmaxf(fmaxf(acc[0][j],acc[1][j]), fmaxf(acc[2][j],acc[3][j]));
        m[j] = mm + b3[chb+j];    // max(a_i)+b == max(a_i+b)
    }
    __syncthreads();
    #pragma unroll
    for(int j=0;j<8;j++) sF[pg*256 + chb + j] = m[j];
    __syncthreads();
    if(tid < 256){
        int ch = tid;   // 256 channels
        float mm = sF[ch];
        #pragma unroll
        for(int g=1;g<16;g++) mm = fmaxf(mm, sF[g*256 + ch]);
        atomicMax(&g_gfenc[b][ch], fenc(mm));
    }
}

// ---------------- attention bias partials: grid (BB, 8), 128 threads ----------------
// Slice s covers 48 of the 384 (gfeat|h) rows of att_w1 (rows 3..386).
__global__ void k_attpre(const float* __restrict__ att_w1, const float* __restrict__ att_b1){
    int b = blockIdx.x, s = blockIdx.y;
    int j = threadIdx.x;
    int r0 = s*48;
    float acc = (s==0) ? att_b1[j] : 0.f;
    #pragma unroll 4
    for(int kk=0;kk<48;kk++){
        int r = r0 + kk;              // 0..383
        float v = (r < GD) ? fdec(g_gfenc[b][r]) : g_h[b][r-GD];
        acc += v * att_w1[(3+r)*128 + j];
    }
    g_attpart[s][b][j] = acc;
}

// ---------------- attention score per point ----------------
__global__ void k_attscore(const float* __restrict__ att_w1, const float* __restrict__ att_w2,
                           const float* __restrict__ att_b2, int N){
    __shared__ float  s_ab[128];
    __shared__ float4 s_pk[128];       // {w1x,w1y,w1z,w2} per hidden unit
    int b = blockIdx.y;
    int tid = threadIdx.x;
    if(tid < 128){
        float a = 0.f;
        #pragma unroll
        for(int s=0;s<8;s++) a += g_attpart[s][b][tid];
        s_ab[tid] = a;
        s_pk[tid] = make_float4(att_w1[tid], att_w1[128+tid], att_w1[256+tid], att_w2[tid]);
    }
    __syncthreads();

    int n = blockIdx.x*256 + tid;
    if(n >= N) return;
    float x = g_canvas[b][n][0], y = g_canvas[b][n][1], z = g_canvas[b][n][2];
    float s = att_b2[0];
    #pragma unroll 4
    for(int jj=0;jj<128;jj++){
        float4 w = s_pk[jj];
        float hv = s_ab[jj] + x*w.x + y*w.y + z*w.z;
        s += fmaxf(hv, 0.f) * w.w;
    }
    g_scores[b][n] = s;
}

// ---------------- fused softmax + center + d2 + exact top-K (smem) ----------------
// one block per batch, 256 threads, dynamic smem = MAXN*4 bytes for d2
__global__ void k_center(int N){
    extern __shared__ float sD[];
    __shared__ float swarp[8];
    __shared__ float s4[8][4];
    __shared__ int   si8[8];
    __shared__ float s_bc[8];
    __shared__ int   s_itot;
    __shared__ unsigned s_eqn;
    __shared__ int   s_eqi[256];
    int b = blockIdx.x, tid = threadIdx.x;
    int lane = tid & 31, wid = tid >> 5;

    // --- max of scores ---
    float m = -FLT_MAX;
    for(int n=tid;n<N;n+=256) m = fmaxf(m, g_scores[b][n]);
    #pragma unroll
    for(int o=16;o;o>>=1) m = fmaxf(m, __shfl_xor_sync(0xffffffffu, m, o));
    if(lane==0) swarp[wid] = m;
    __syncthreads();
    if(tid==0){
        float mm = swarp[0];
        for(int i=1;i<8;i++) mm = fmaxf(mm, swarp[i]);
        s_bc[0] = mm;
    }
    __syncthreads();
    float mx = s_bc[0];

    // --- exp sums + weighted coordinate sums ---
    float se=0,sx=0,sy=0,sz=0;
    for(int n=tid;n<N;n+=256){
        float e = expf(g_scores[b][n]-mx);
        se += e;
        sx += e*g_canvas[b][n][0];
        sy += e*g_canvas[b][n][1];
        sz += e*g_canvas[b][n][2];
    }
    #pragma unroll
    for(int o=16;o;o>>=1){
        se += __shfl_xor_sync(0xffffffffu, se, o);
        sx += __shfl_xor_sync(0xffffffffu, sx, o);
        sy += __shfl_xor_sync(0xffffffffu, sy, o);
        sz += __shfl_xor_sync(0xffffffffu, sz, o);
    }
    if(lane==0){ s4[wid][0]=se; s4[wid][1]=sx; s4[wid][2]=sy; s4[wid][3]=sz; }
    __syncthreads();
    if(tid==0){
        float te=0,tx=0,ty=0,tz=0;
        for(int i=0;i<8;i++){ te+=s4[i][0]; tx+=s4[i][1]; ty+=s4[i][2]; tz+=s4[i][3]; }
        float cx=tx/te, cy=ty/te, cz=tz/te;
        s_bc[1]=cx; s_bc[2]=cy; s_bc[3]=cz;
        g_center[b][0]=cx; g_center[b][1]=cy; g_center[b][2]=cz;
        s_eqn = 0;
    }
    __syncthreads();
    float cx=s_bc[1], cy=s_bc[2], cz=s_bc[3];

    // --- squared distances into smem (sqrt monotone -> same top-K ordering) ---
    for(int n=tid;n<N;n+=256){
        float dx=g_canvas[b][n][0]-cx, dy=g_canvas[b][n][1]-cy, dz=g_canvas[b][n][2]-cz;
        sD[n] = dx*dx+dy*dy+dz*dz;
    }
    __syncthreads();

    // --- binary search on (nonneg) float bits for K-th smallest ---
    unsigned lo=0u, hi=0x7f800000u;
    while(lo < hi){
        unsigned mid = lo + ((hi-lo)>>1);
        int c=0;
        for(int n=tid;n<N;n+=256) c += (__float_as_uint(sD[n]) <= mid);
        #pragma unroll
        for(int o=16;o;o>>=1) c += __shfl_xor_sync(0xffffffffu, c, o);
        if(lane==0) si8[wid]=c;
        __syncthreads();
        if(tid==0){ int t=0; for(int i=0;i<8;i++) t+=si8[i]; s_itot=t; }
        __syncthreads();
        if(s_itot >= KSEL) hi = mid; else lo = mid+1;
    }
    unsigned u = lo;

    // --- sums of strictly-below + boundary ties (index order matches lax.top_k) ---
    float ax=0,ay=0,az=0; int c=0;
    for(int n=tid;n<N;n+=256){
        unsigned bits = __float_as_uint(sD[n]);
        if(bits < u){
            c++; ax+=g_canvas[b][n][0]; ay+=g_canvas[b][n][1]; az+=g_canvas[b][n][2];
        }
        if(bits == u){
            unsigned p = atomicAdd(&s_eqn, 1u);
            if(p < 256) s_eqi[p] = n;
        }
    }
    #pragma unroll
    for(int o=16;o;o>>=1){
        c  += __shfl_xor_sync(0xffffffffu, c, o);
        ax += __shfl_xor_sync(0xffffffffu, ax, o);
        ay += __shfl_xor_sync(0xffffffffu, ay, o);
        az += __shfl_xor_sync(0xffffffffu, az, o);
    }
    if(lane==0){ si8[wid]=c; s4[wid][0]=ax; s4[wid][1]=ay; s4[wid][2]=az; }
    __syncthreads();
    if(tid==0){
        int tc=0; float tx=0,ty=0,tz=0;
        for(int i=0;i<8;i++){ tc+=si8[i]; tx+=s4[i][0]; ty+=s4[i][1]; tz+=s4[i][2]; }
        int r = KSEL - tc;                 // boundary elems needed, in index order
        int mcount = min((int)s_eqn, 256);
        for(int it=0; it<r; it++){
            int best=-1, bi=0x7fffffff;
            for(int q=0;q<mcount;q++){ int v=s_eqi[q]; if(v>=0 && v<bi){bi=v;best=q;} }
            if(best<0) break;
            s_eqi[best] = -1;
            tx += g_canvas[b][bi][0]; ty += g_canvas[b][bi][1]; tz += g_canvas[b][bi][2];
        }
        float inv = 1.f/KSEL;
        g_patch[b][0] = tx*inv - cx;
        g_patch[b][1] = ty*inv - cy;
        g_patch[b][2] = tz*inv - cz;
    }
}

// ---------------- fused LSTM gates + cell update + refine layer 1 (one block, 512 thr) ----
__global__ void k_state(const float* __restrict__ wih, const float* __restrict__ whh,
                        const float* __restrict__ bih, const float* __restrict__ bhh,
                        const float* __restrict__ ref_w1, const float* __restrict__ ref_b1){
    __shared__ float s_in[BB][262];
    __shared__ float s_h[BB][HD];
    __shared__ float s_g[BB][4*HD];
    __shared__ float s_hn[BB][HD];
    int tid = threadIdx.x;  // 512
    for(int i=tid;i<BB*262;i+=512){
        int b=i/262, k=i-b*262;
        float v;
        if(k < GD)        v = fdec(g_gfenc[b][k]);
        else if(k < GD+3) v = g_center[b][k-GD];
        else              v = g_patch[b][k-GD-3];
        s_in[b][k]=v;
    }
    for(int i=tid;i<BB*HD;i+=512) s_h[i>>7][i&127]=g_h[i>>7][i&127];
    __syncthreads();
    {   // gates: each thread computes one of 512 gate outputs for all 4 batches
        int j = tid;
        float base = bih[j] + bhh[j];
        float a0=base,a1=base,a2=base,a3=base;
        #pragma unroll 2
        for(int k=0;k<262;k++){
            float w = wih[k*512 + j];
            a0 += s_in[0][k]*w; a1 += s_in[1][k]*w; a2 += s_in[2][k]*w; a3 += s_in[3][k]*w;
        }
        #pragma unroll 2
        for(int k=0;k<HD;k++){
            float w = whh[k*512 + j];
            a0 += s_h[0][k]*w; a1 += s_h[1][k]*w; a2 += s_h[2][k]*w; a3 += s_h[3][k]*w;
        }
        s_g[0][j]=a0; s_g[1][j]=a1; s_g[2][j]=a2; s_g[3][j]=a3;
    }
    __syncthreads();
    {   // LSTM cell update
        int b = tid>>7, j = tid&127;
        float gi=s_g[b][j], gf=s_g[b][HD+j], gg=s_g[b][2*HD+j], go=s_g[b][3*HD+j];
        float sgi=1.f/(1.f+expf(-gi)), sgf=1.f/(1.f+expf(-gf)), sgo=1.f/(1.f+expf(-go));
        float cc = sgf*g_c[b][j] + sgi*tanhf(gg);
        g_c[b][j] = cc;
        float h = sgo*tanhf(cc);
        g_h[b][j] = h;
        s_hn[b][j] = h;
    }
    __syncthreads();
    {   // refine layer 1
        int b = tid>>7, j = tid&127;
        float a = ref_b1[j];
        #pragma unroll 2
        for(int k=0;k<HD;k++) a += s_hn[b][k]*ref_w1[k*128+j];
        g_hid[b][j] = fmaxf(a, 0.f);
    }
}

// ---------------- refine decoder layer 2 -> new canvas points ----------------
__global__ void k_ref2(const float* __restrict__ ref_w2, const float* __restrict__ ref_b2, int N){
    int o = blockIdx.x*256 + threadIdx.x;
    if(o >= BB*REFO) return;
    int b = o/REFO, q = o - b*REFO;
    float a = ref_b2[q];
    const float* h = g_hid[b];
    #pragma unroll 4
    for(int k=0;k<HD;k++) a += h[k]*ref_w2[k*REFO + q];
    int pt = q/3, d = q - 3*pt;
    g_canvas[b][N+pt][d] = a*0.02f + g_center[b][d];
}

// ---------------- chamfer: expansion form (x2+y2-2xy), scalar ----------------
#define CTI 2048
__global__ void k_cham(const float* __restrict__ gt, int xsel, int xoff, int Nx,
                       int ysel, int yoff, int Ny, int ai){
    __shared__ float s0[CTI];
    __shared__ float s1[CTI];
    __shared__ float s2[CTI];
    __shared__ float sc[CTI];
    __shared__ float red[256];
    int b = blockIdx.y, tid = threadIdx.x;
    int n = blockIdx.x*256 + tid;
    bool act = n < Nx;
    float x0=0,x1=0,x2=0;
    if(act){
        const float* p = (xsel==0) ? &g_canvas[b][xoff+n][0]
                                   : gt + ((size_t)b*NP0 + xoff + n)*3;
        x0=p[0]; x1=p[1]; x2=p[2];
    }
    float xx = x0*x0 + x1*x1 + x2*x2;
    float mn = FLT_MAX;
    for(int t=0;t<Ny;t+=CTI){
        int cnt = min(CTI, Ny-t);
        __syncthreads();
        const float* ys = (ysel==0) ? &g_canvas[b][yoff+t][0]
                                    : gt + ((size_t)b*NP0 + yoff + t)*3;
        for(int i=tid;i<cnt;i+=256){
            float y0=ys[3*i], y1=ys[3*i+1], y2=ys[3*i+2];
            s0[i]=y0; s1[i]=y1; s2[i]=y2;
            sc[i]=y0*y0+y1*y1+y2*y2;
        }
        __syncthreads();
        if(act){
            #pragma unroll 4
            for(int j=0;j<cnt;j++){
                float dot = fmaf(x0, s0[j], fmaf(x1, s1[j], x2*s2[j]));
                float v   = fmaf(-2.f, dot, sc[j]);   // yy - 2*dot
                mn = fminf(mn, v);
            }
        }
    }
    red[tid] = act ? (xx + mn) : 0.f;
    __syncthreads();
    for(int s=128;s>0;s>>=1){ if(tid<s) red[tid]+=red[tid+s]; __syncthreads(); }
    if(tid==0) atomicAdd(&g_acc[ai], (double)red[0]);
}

__global__ void k_final(float* __restrict__ out){
    double cd_in  = g_acc[0]/(4.0*NP0)          + g_acc[1]/(4.0*NP0);
    double cd_new = g_acc[2]/(4.0*(10.0*NEWP))  + g_acc[3]/(4.0*NP0);
    out[0] = (float)(0.1*cd_in + 1.0*cd_new);
}

// ---------------- host launch ----------------
extern "C" void kernel_launch(void* const* d_in, const int* in_sizes, int n_in,
                              void* d_out, int out_size){
    const float* points   = (const float*)d_in[0];
    const float* gt       = (const float*)d_in[1];
    const float* enc_w1   = (const float*)d_in[2];
    const float* enc_b1   = (const float*)d_in[3];
    const float* enc_w2   = (const float*)d_in[4];
    const float* enc_b2   = (const float*)d_in[5];
    const float* enc_w3   = (const float*)d_in[6];
    const float* enc_b3   = (const float*)d_in[7];
    const float* att_w1   = (const float*)d_in[8];
    const float* att_b1   = (const float*)d_in[9];
    const float* att_w2   = (const float*)d_in[10];
    const float* att_b2   = (const float*)d_in[11];
    const float* lstm_wih = (const float*)d_in[12];
    const float* lstm_whh = (const float*)d_in[13];
    const float* lstm_bih = (const float*)d_in[14];
    const float* lstm_bhh = (const float*)d_in[15];
    const float* ref_w1   = (const float*)d_in[16];
    const float* ref_b1   = (const float*)d_in[17];
    const float* ref_w2   = (const float*)d_in[18];
    const float* ref_b2   = (const float*)d_in[19];

    // opt-in dynamic smem for k_center (d2 array up to ~62KB); idempotent, capture-safe
    cudaFuncSetAttribute(k_center, cudaFuncAttributeMaxDynamicSharedMemorySize, 64*1024);

    k_init<<<(BB*NP0*3 + 255)/256, 256>>>(points);

    int N = NP0;
    for(int s=0;s<NSTEPS;s++){
        int P = BB*N;
        k_enc12<<<(P+255)/256, 256>>>(enc_w1, enc_b1, enc_w2, enc_b2, N);
        dim3 g3(BB, N/64);
        k_enc3<<<g3, 512>>>(enc_w3, enc_b3);
        k_attpre<<<dim3(BB,8), 128>>>(att_w1, att_b1);
        k_attscore<<<dim3((N+255)/256, BB), 256>>>(att_w1, att_w2, att_b2, N);
        k_center<<<BB, 256, MAXN*4>>>(N);
        k_state<<<1,512>>>(lstm_wih, lstm_whh, lstm_bih, lstm_bhh, ref_w1, ref_b1);
        k_ref2<<<(BB*REFO+255)/256, 256>>>(ref_w2, ref_b2, N);
        N += NEWP;
    }

    int NN = N - NP0;  // 11520 new points
    k_cham<<<dim3((NP0+255)/256, BB), 256>>>(gt, 0, 0,   NP0, 1, 0,   NP0, 0);
    k_cham<<<dim3((NP0+255)/256, BB), 256>>>(gt, 1, 0,   NP0, 0, 0,   NP0, 1);
    k_cham<<<dim3((NN +255)/256, BB), 256>>>(gt, 0, NP0, NN,  1, 0,   NP0, 2);
    k_cham<<<dim3((NP0+255)/256, BB), 256>>>(gt, 1, 0,   NP0, 0, NP0, NN,  3);

    k_final<<<1,1>>>((float*)d_out);
}

// round 5
// speedup vs baseline: 1.2572x; 1.2572x over previous
#include <cuda_runtime.h>
#include <math.h>
#include <float.h>

#define BB 4
#define NP0 4096
#define NEWP 1152
#define MAXN (NP0 + 10*NEWP)     // 15616
#define GD 256
#define HD 128
#define KSEL 64
#define NSTEPS 10
#define REFO (NEWP*3)            // 3456

// ---------------- device scratch (static: no allocation) ----------------
__device__ float    g_canvas[BB][MAXN][3];
__device__ float    g_F2T[128][BB*MAXN];      // encoder layer-2 activations, transposed
__device__ unsigned g_gfenc[BB][GD];
__device__ float    g_h[BB][HD];
__device__ float    g_c[BB][HD];
__device__ float    g_scores[BB][MAXN];
__device__ float    g_center[BB][3];
__device__ float    g_patch[BB][3];
__device__ float    g_hid[BB][HD];
__device__ float    g_attpart[32][BB][128];   // partial bias sums
__device__ double   g_acc[4];

// monotone float<->uint encoding (for atomicMax over signed floats)
__device__ __forceinline__ unsigned fenc(float f){
    unsigned u = __float_as_uint(f);
    return (u & 0x80000000u) ? ~u : (u | 0x80000000u);
}
__device__ __forceinline__ float fdec(unsigned e){
    unsigned u = (e & 0x80000000u) ? (e & 0x7fffffffu) : ~e;
    return __uint_as_float(u);
}

// ---------------- init ----------------
__global__ void k_init(const float* __restrict__ points){
    int i = blockIdx.x*blockDim.x + threadIdx.x;
    if(i < BB*NP0*3){
        int b = i/(NP0*3); int r = i - b*(NP0*3);
        g_canvas[b][r/3][r%3] = points[i];
    }
    if(i < BB*HD){ g_h[i/HD][i%HD] = 0.f; g_c[i/HD][i%HD] = 0.f; }
    if(i < 4) g_acc[i] = 0.0;
}

// ---------------- encoder layers 1-2 (per point), fused gfeat re-init ----------------
__global__ void k_enc12(const float* __restrict__ w1, const float* __restrict__ b1,
                        const float* __restrict__ w2, const float* __restrict__ b2, int N){
    __shared__ float s_w1[192];
    __shared__ float s_b1[64];
    __shared__ float s_w2[64*128];
    __shared__ float s_b2[128];
    int tid = threadIdx.x;
    if(blockIdx.x == 0){  // re-init gfeat max accumulators for this step
        for(int i=tid;i<BB*GD;i+=256) ((unsigned*)g_gfenc)[i] = fenc(-FLT_MAX);
    }
    for(int i=tid;i<192;i+=256) s_w1[i]=w1[i];
    if(tid<64)  s_b1[tid]=b1[tid];
    if(tid<128) s_b2[tid]=b2[tid];
    for(int i=tid;i<8192;i+=256) s_w2[i]=w2[i];
    __syncthreads();

    int p = blockIdx.x*256 + tid;
    if(p >= BB*N) return;
    int b = p / N, n = p - b*N;
    float x = g_canvas[b][n][0], y = g_canvas[b][n][1], z = g_canvas[b][n][2];

    float f1[64];
    #pragma unroll
    for(int o=0;o<64;o++)
        f1[o] = fmaxf(0.f, s_b1[o] + x*s_w1[o] + y*s_w1[64+o] + z*s_w1[128+o]);

    size_t col = (size_t)b*MAXN + n;
    for(int j=0;j<128;j+=4){
        float a0=s_b2[j], a1=s_b2[j+1], a2=s_b2[j+2], a3=s_b2[j+3];
        #pragma unroll
        for(int k=0;k<64;k++){
            float4 w = *(const float4*)&s_w2[k*128 + j];
            float f = f1[k];
            a0 += f*w.x; a1 += f*w.y; a2 += f*w.z; a3 += f*w.w;
        }
        g_F2T[j  ][col] = fmaxf(a0,0.f);
        g_F2T[j+1][col] = fmaxf(a1,0.f);
        g_F2T[j+2][col] = fmaxf(a2,0.f);
        g_F2T[j+3][col] = fmaxf(a3,0.f);
    }
}

// ---------------- encoder layer 3 GEMM + channel max (gfeat) ----------------
// grid (BB, N/64), block 256.  Tile: 64 points x 256 channels.
// K=128 staged through smem in 4 chunks of 32 -> inner loop is pure LDS+FFMA.
// Thread (lane,pg) owns channels {4*lane..+3, 128+4*lane..+3} x points pg*8..+7.
__global__ void __launch_bounds__(256,2)
k_enc3(const float* __restrict__ w3, const float* __restrict__ b3){
    __shared__ float sW[32*256];   // [kk][ch]  32KB
    __shared__ float sF[32*64];    // [kk][p]    8KB  (reused as reduce buf)
    int b = blockIdx.x;
    int pbase = blockIdx.y*64;
    int tid = threadIdx.x;
    int lane = tid & 31, pg = tid >> 5;
    int c0 = lane*4, c1 = 128 + lane*4;
    size_t base = (size_t)b*MAXN + pbase;

    float acc[8][8];
    #pragma unroll
    for(int i=0;i<8;i++)
        #pragma unroll
        for(int j=0;j<8;j++) acc[i][j]=0.f;

    for(int kc=0;kc<128;kc+=32){
        __syncthreads();
        {   // stage w3 chunk: rows kc..kc+31 (contiguous 8192 floats)
            const float4* wsrc = (const float4*)(w3 + (size_t)kc*256);
            float4* wdst = (float4*)sW;
            #pragma unroll
            for(int i=0;i<8;i++) wdst[tid + i*256] = wsrc[tid + i*256];
        }
        {   // stage F2T chunk: 32 rows x 64 points
            #pragma unroll
            for(int i=0;i<8;i++){
                int idx = tid + i*256;
                int k = idx>>6, p = idx&63;
                sF[idx] = g_F2T[kc+k][base+p];
            }
        }
        __syncthreads();
        #pragma unroll 4
        for(int k=0;k<32;k++){
            float4 wa = *(const float4*)&sW[k*256 + c0];
            float4 wb = *(const float4*)&sW[k*256 + c1];
            float4 fa = *(const float4*)&sF[k*64 + pg*8];
            float4 fb = *(const float4*)&sF[k*64 + pg*8 + 4];
            float f[8] = {fa.x,fa.y,fa.z,fa.w,fb.x,fb.y,fb.z,fb.w};
            float w[8] = {wa.x,wa.y,wa.z,wa.w,wb.x,wb.y,wb.z,wb.w};
            #pragma unroll
            for(int i=0;i<8;i++)
                #pragma unroll
                for(int j=0;j<8;j++)
                    acc[i][j] += f[i]*w[j];
        }
    }
    // per-thread max over 8 points; +bias (max(a)+b == max(a+b))
    float m[8];
    #pragma unroll
    for(int j=0;j<8;j++){
        float mm = acc[0][j];
        #pragma unroll
        for(int i=1;i<8;i++) mm = fmaxf(mm, acc[i][j]);
        int ch = (j<4) ? (c0+j) : (c1+j-4);
        m[j] = mm + b3[ch];
    }
    __syncthreads();
    #pragma unroll
    for(int j=0;j<8;j++){
        int ch = (j<4) ? (c0+j) : (c1+j-4);
        sF[pg*256 + ch] = m[j];
    }
    __syncthreads();
    {
        int ch = tid;   // 256 channels
        float mm = sF[ch];
        #pragma unroll
        for(int g=1;g<8;g++) mm = fmaxf(mm, sF[g*256 + ch]);
        atomicMax(&g_gfenc[b][ch], fenc(mm));
    }
}

// ---------------- attention bias partials: grid (BB, 32), 128 threads ----------------
// Slice s covers 12 of the 384 (gfeat|h) rows of att_w1 (rows 3..386).
__global__ void k_attpre(const float* __restrict__ att_w1, const float* __restrict__ att_b1){
    int b = blockIdx.x, s = blockIdx.y;
    int j = threadIdx.x;
    int r0 = s*12;
    float acc = (s==0) ? att_b1[j] : 0.f;
    #pragma unroll
    for(int kk=0;kk<12;kk++){
        int r = r0 + kk;              // 0..383
        float v = (r < GD) ? fdec(g_gfenc[b][r]) : g_h[b][r-GD];
        acc += v * att_w1[(3+r)*128 + j];
    }
    g_attpart[s][b][j] = acc;
}

// ---------------- attention score per point ----------------
__global__ void k_attscore(const float* __restrict__ att_w1, const float* __restrict__ att_w2,
                           const float* __restrict__ att_b2, int N){
    __shared__ float  s_ab[128];
    __shared__ float4 s_pk[128];       // {w1x,w1y,w1z,w2} per hidden unit
    int b = blockIdx.y;
    int tid = threadIdx.x;
    if(tid < 128){
        float a = 0.f;
        #pragma unroll
        for(int s=0;s<32;s++) a += g_attpart[s][b][tid];
        s_ab[tid] = a;
        s_pk[tid] = make_float4(att_w1[tid], att_w1[128+tid], att_w1[256+tid], att_w2[tid]);
    }
    __syncthreads();

    int n = blockIdx.x*256 + tid;
    if(n >= N) return;
    float x = g_canvas[b][n][0], y = g_canvas[b][n][1], z = g_canvas[b][n][2];
    float s = att_b2[0];
    #pragma unroll 4
    for(int jj=0;jj<128;jj++){
        float4 w = s_pk[jj];
        float hv = s_ab[jj] + x*w.x + y*w.y + z*w.z;
        s += fmaxf(hv, 0.f) * w.w;
    }
    g_scores[b][n] = s;
}

// ---------------- fused softmax + center + d2 + exact top-K (smem) ----------------
// one block per batch, 256 threads, dynamic smem = MAXN*4 bytes for d2
__global__ void k_center(int N){
    extern __shared__ float sD[];
    __shared__ float swarp[8];
    __shared__ float s4[8][4];
    __shared__ int   si8[8];
    __shared__ float s_bc[8];
    __shared__ int   s_itot;
    __shared__ unsigned s_eqn;
    __shared__ int   s_eqi[256];
    int b = blockIdx.x, tid = threadIdx.x;
    int lane = tid & 31, wid = tid >> 5;

    // --- max of scores ---
    float m = -FLT_MAX;
    for(int n=tid;n<N;n+=256) m = fmaxf(m, g_scores[b][n]);
    #pragma unroll
    for(int o=16;o;o>>=1) m = fmaxf(m, __shfl_xor_sync(0xffffffffu, m, o));
    if(lane==0) swarp[wid] = m;
    __syncthreads();
    if(tid==0){
        float mm = swarp[0];
        for(int i=1;i<8;i++) mm = fmaxf(mm, swarp[i]);
        s_bc[0] = mm;
    }
    __syncthreads();
    float mx = s_bc[0];

    // --- exp sums + weighted coordinate sums ---
    float se=0,sx=0,sy=0,sz=0;
    for(int n=tid;n<N;n+=256){
        float e = expf(g_scores[b][n]-mx);
        se += e;
        sx += e*g_canvas[b][n][0];
        sy += e*g_canvas[b][n][1];
        sz += e*g_canvas[b][n][2];
    }
    #pragma unroll
    for(int o=16;o;o>>=1){
        se += __shfl_xor_sync(0xffffffffu, se, o);
        sx += __shfl_xor_sync(0xffffffffu, sx, o);
        sy += __shfl_xor_sync(0xffffffffu, sy, o);
        sz += __shfl_xor_sync(0xffffffffu, sz, o);
    }
    if(lane==0){ s4[wid][0]=se; s4[wid][1]=sx; s4[wid][2]=sy; s4[wid][3]=sz; }
    __syncthreads();
    if(tid==0){
        float te=0,tx=0,ty=0,tz=0;
        for(int i=0;i<8;i++){ te+=s4[i][0]; tx+=s4[i][1]; ty+=s4[i][2]; tz+=s4[i][3]; }
        float cx=tx/te, cy=ty/te, cz=tz/te;
        s_bc[1]=cx; s_bc[2]=cy; s_bc[3]=cz;
        g_center[b][0]=cx; g_center[b][1]=cy; g_center[b][2]=cz;
        s_eqn = 0;
    }
    __syncthreads();
    float cx=s_bc[1], cy=s_bc[2], cz=s_bc[3];

    // --- squared distances into smem (sqrt monotone -> same top-K ordering) ---
    for(int n=tid;n<N;n+=256){
        float dx=g_canvas[b][n][0]-cx, dy=g_canvas[b][n][1]-cy, dz=g_canvas[b][n][2]-cz;
        sD[n] = dx*dx+dy*dy+dz*dz;
    }
    __syncthreads();

    // --- binary search on (nonneg) float bits for K-th smallest ---
    unsigned lo=0u, hi=0x7f800000u;
    while(lo < hi){
        unsigned mid = lo + ((hi-lo)>>1);
        int c=0;
        for(int n=tid;n<N;n+=256) c += (__float_as_uint(sD[n]) <= mid);
        #pragma unroll
        for(int o=16;o;o>>=1) c += __shfl_xor_sync(0xffffffffu, c, o);
        if(lane==0) si8[wid]=c;
        __syncthreads();
        if(tid==0){ int t=0; for(int i=0;i<8;i++) t+=si8[i]; s_itot=t; }
        __syncthreads();
        if(s_itot >= KSEL) hi = mid; else lo = mid+1;
    }
    unsigned u = lo;

    // --- sums of strictly-below + boundary ties (index order matches lax.top_k) ---
    float ax=0,ay=0,az=0; int c=0;
    for(int n=tid;n<N;n+=256){
        unsigned bits = __float_as_uint(sD[n]);
        if(bits < u){
            c++; ax+=g_canvas[b][n][0]; ay+=g_canvas[b][n][1]; az+=g_canvas[b][n][2];
        }
        if(bits == u){
            unsigned p = atomicAdd(&s_eqn, 1u);
            if(p < 256) s_eqi[p] = n;
        }
    }
    #pragma unroll
    for(int o=16;o;o>>=1){
        c  += __shfl_xor_sync(0xffffffffu, c, o);
        ax += __shfl_xor_sync(0xffffffffu, ax, o);
        ay += __shfl_xor_sync(0xffffffffu, ay, o);
        az += __shfl_xor_sync(0xffffffffu, az, o);
    }
    if(lane==0){ si8[wid]=c; s4[wid][0]=ax; s4[wid][1]=ay; s4[wid][2]=az; }
    __syncthreads();
    if(tid==0){
        int tc=0; float tx=0,ty=0,tz=0;
        for(int i=0;i<8;i++){ tc+=si8[i]; tx+=s4[i][0]; ty+=s4[i][1]; tz+=s4[i][2]; }
        int r = KSEL - tc;                 // boundary elems needed, in index order
        int mcount = min((int)s_eqn, 256);
        for(int it=0; it<r; it++){
            int best=-1, bi=0x7fffffff;
            for(int q=0;q<mcount;q++){ int v=s_eqi[q]; if(v>=0 && v<bi){bi=v;best=q;} }
            if(best<0) break;
            s_eqi[best] = -1;
            tx += g_canvas[b][bi][0]; ty += g_canvas[b][bi][1]; tz += g_canvas[b][bi][2];
        }
        float inv = 1.f/KSEL;
        g_patch[b][0] = tx*inv - cx;
        g_patch[b][1] = ty*inv - cy;
        g_patch[b][2] = tz*inv - cz;
    }
}

// ---------------- fused LSTM gates + cell update + refine layer 1 (one block, 512 thr) ----
__global__ void k_state(const float* __restrict__ wih, const float* __restrict__ whh,
                        const float* __restrict__ bih, const float* __restrict__ bhh,
                        const float* __restrict__ ref_w1, const float* __restrict__ ref_b1){
    __shared__ float s_in[BB][262];
    __shared__ float s_h[BB][HD];
    __shared__ float s_g[BB][4*HD];
    __shared__ float s_hn[BB][HD];
    int tid = threadIdx.x;  // 512
    for(int i=tid;i<BB*262;i+=512){
        int b=i/262, k=i-b*262;
        float v;
        if(k < GD)        v = fdec(g_gfenc[b][k]);
        else if(k < GD+3) v = g_center[b][k-GD];
        else              v = g_patch[b][k-GD-3];
        s_in[b][k]=v;
    }
    for(int i=tid;i<BB*HD;i+=512) s_h[i>>7][i&127]=g_h[i>>7][i&127];
    __syncthreads();
    {   // gates: each thread computes one of 512 gate outputs for all 4 batches
        int j = tid;
        float base = bih[j] + bhh[j];
        float a0=base,a1=base,a2=base,a3=base;
        #pragma unroll 2
        for(int k=0;k<262;k++){
            float w = wih[k*512 + j];
            a0 += s_in[0][k]*w; a1 += s_in[1][k]*w; a2 += s_in[2][k]*w; a3 += s_in[3][k]*w;
        }
        #pragma unroll 2
        for(int k=0;k<HD;k++){
            float w = whh[k*512 + j];
            a0 += s_h[0][k]*w; a1 += s_h[1][k]*w; a2 += s_h[2][k]*w; a3 += s_h[3][k]*w;
        }
        s_g[0][j]=a0; s_g[1][j]=a1; s_g[2][j]=a2; s_g[3][j]=a3;
    }
    __syncthreads();
    {   // LSTM cell update
        int b = tid>>7, j = tid&127;
        float gi=s_g[b][j], gf=s_g[b][HD+j], gg=s_g[b][2*HD+j], go=s_g[b][3*HD+j];
        float sgi=1.f/(1.f+expf(-gi)), sgf=1.f/(1.f+expf(-gf)), sgo=1.f/(1.f+expf(-go));
        float cc = sgf*g_c[b][j] + sgi*tanhf(gg);
        g_c[b][j] = cc;
        float h = sgo*tanhf(cc);
        g_h[b][j] = h;
        s_hn[b][j] = h;
    }
    __syncthreads();
    {   // refine layer 1
        int b = tid>>7, j = tid&127;
        float a = ref_b1[j];
        #pragma unroll 2
        for(int k=0;k<HD;k++) a += s_hn[b][k]*ref_w1[k*128+j];
        g_hid[b][j] = fmaxf(a, 0.f);
    }
}

// ---------------- refine decoder layer 2 -> new canvas points ----------------
__global__ void k_ref2(const float* __restrict__ ref_w2, const float* __restrict__ ref_b2, int N){
    int o = blockIdx.x*256 + threadIdx.x;
    if(o >= BB*REFO) return;
    int b = o/REFO, q = o - b*REFO;
    float a = ref_b2[q];
    const float* h = g_hid[b];
    #pragma unroll 4
    for(int k=0;k<HD;k++) a += h[k]*ref_w2[k*REFO + q];
    int pt = q/3, d = q - 3*pt;
    g_canvas[b][N+pt][d] = a*0.02f + g_center[b][d];
}

// ---------------- chamfer: expansion form (x2+y2-2xy), scalar ----------------
#define CTI 2048
__global__ void k_cham(const float* __restrict__ gt, int xsel, int xoff, int Nx,
                       int ysel, int yoff, int Ny, int ai){
    __shared__ float s0[CTI];
    __shared__ float s1[CTI];
    __shared__ float s2[CTI];
    __shared__ float sc[CTI];
    __shared__ float red[256];
    int b = blockIdx.y, tid = threadIdx.x;
    int n = blockIdx.x*256 + tid;
    bool act = n < Nx;
    float x0=0,x1=0,x2=0;
    if(act){
        const float* p = (xsel==0) ? &g_canvas[b][xoff+n][0]
                                   : gt + ((size_t)b*NP0 + xoff + n)*3;
        x0=p[0]; x1=p[1]; x2=p[2];
    }
    float xx = x0*x0 + x1*x1 + x2*x2;
    float mn = FLT_MAX;
    for(int t=0;t<Ny;t+=CTI){
        int cnt = min(CTI, Ny-t);
        __syncthreads();
        const float* ys = (ysel==0) ? &g_canvas[b][yoff+t][0]
                                    : gt + ((size_t)b*NP0 + yoff + t)*3;
        for(int i=tid;i<cnt;i+=256){
            float y0=ys[3*i], y1=ys[3*i+1], y2=ys[3*i+2];
            s0[i]=y0; s1[i]=y1; s2[i]=y2;
            sc[i]=y0*y0+y1*y1+y2*y2;
        }
        __syncthreads();
        if(act){
            #pragma unroll 4
            for(int j=0;j<cnt;j++){
                float dot = fmaf(x0, s0[j], fmaf(x1, s1[j], x2*s2[j]));
                float v   = fmaf(-2.f, dot, sc[j]);   // yy - 2*dot
                mn = fminf(mn, v);
            }
        }
    }
    red[tid] = act ? (xx + mn) : 0.f;
    __syncthreads();
    for(int s=128;s>0;s>>=1){ if(tid<s) red[tid]+=red[tid+s]; __syncthreads(); }
    if(tid==0) atomicAdd(&g_acc[ai], (double)red[0]);
}

__global__ void k_final(float* __restrict__ out){
    double cd_in  = g_acc[0]/(4.0*NP0)          + g_acc[1]/(4.0*NP0);
    double cd_new = g_acc[2]/(4.0*(10.0*NEWP))  + g_acc[3]/(4.0*NP0);
    out[0] = (float)(0.1*cd_in + 1.0*cd_new);
}

// ---------------- host launch ----------------
extern "C" void kernel_launch(void* const* d_in, const int* in_sizes, int n_in,
                              void* d_out, int out_size){
    const float* points   = (const float*)d_in[0];
    const float* gt       = (const float*)d_in[1];
    const float* enc_w1   = (const float*)d_in[2];
    const float* enc_b1   = (const float*)d_in[3];
    const float* enc_w2   = (const float*)d_in[4];
    const float* enc_b2   = (const float*)d_in[5];
    const float* enc_w3   = (const float*)d_in[6];
    const float* enc_b3   = (const float*)d_in[7];
    const float* att_w1   = (const float*)d_in[8];
    const float* att_b1   = (const float*)d_in[9];
    const float* att_w2   = (const float*)d_in[10];
    const float* att_b2   = (const float*)d_in[11];
    const float* lstm_wih = (const float*)d_in[12];
    const float* lstm_whh = (const float*)d_in[13];
    const float* lstm_bih = (const float*)d_in[14];
    const float* lstm_bhh = (const float*)d_in[15];
    const float* ref_w1   = (const float*)d_in[16];
    const float* ref_b1   = (const float*)d_in[17];
    const float* ref_w2   = (const float*)d_in[18];
    const float* ref_b2   = (const float*)d_in[19];

    // opt-in dynamic smem for k_center (d2 array up to ~62KB); idempotent, capture-safe
    cudaFuncSetAttribute(k_center, cudaFuncAttributeMaxDynamicSharedMemorySize, 64*1024);

    k_init<<<(BB*NP0*3 + 255)/256, 256>>>(points);

    int N = NP0;
    for(int s=0;s<NSTEPS;s++){
        int P = BB*N;
        k_enc12<<<(P+255)/256, 256>>>(enc_w1, enc_b1, enc_w2, enc_b2, N);
        dim3 g3(BB, N/64);
        k_enc3<<<g3, 256>>>(enc_w3, enc_b3);
        k_attpre<<<dim3(BB,32), 128>>>(att_w1, att_b1);
        k_attscore<<<dim3((N+255)/256, BB), 256>>>(att_w1, att_w2, att_b2, N);
        k_center<<<BB, 256, MAXN*4>>>(N);
        k_state<<<1,512>>>(lstm_wih, lstm_whh, lstm_bih, lstm_bhh, ref_w1, ref_b1);
        k_ref2<<<(BB*REFO+255)/256, 256>>>(ref_w2, ref_b2, N);
        N += NEWP;
    }

    int NN = N - NP0;  // 11520 new points
    k_cham<<<dim3((NP0+255)/256, BB), 256>>>(gt, 0, 0,   NP0, 1, 0,   NP0, 0);
    k_cham<<<dim3((NP0+255)/256, BB), 256>>>(gt, 1, 0,   NP0, 0, 0,   NP0, 1);
    k_cham<<<dim3((NN +255)/256, BB), 256>>>(gt, 0, NP0, NN,  1, 0,   NP0, 2);
    k_cham<<<dim3((NP0+255)/256, BB), 256>>>(gt, 1, 0,   NP0, 0, NP0, NN,  3);

    k_final<<<1,1>>>((float*)d_out);
}

// round 6
// speedup vs baseline: 1.3689x; 1.0889x over previous
#include <cuda_runtime.h>
#include <math.h>
#include <float.h>

#define BB 4
#define NP0 4096
#define NEWP 1152
#define MAXN (NP0 + 10*NEWP)     // 15616
#define GD 256
#define HD 128
#define KSEL 64
#define NSTEPS 10
#define REFO (NEWP*3)            // 3456

// ---------------- device scratch (static: no allocation) ----------------
__device__ float    g_canvas[BB][MAXN][3];
__device__ float    g_F2T[128][BB*MAXN];      // encoder layer-2 activations, transposed
__device__ unsigned g_gfenc[BB][GD];
__device__ float    g_h[BB][HD];
__device__ float    g_c[BB][HD];
__device__ float    g_scores[BB][MAXN];
__device__ float    g_center[BB][3];
__device__ float    g_patch[BB][3];
__device__ float    g_hid[BB][HD];
__device__ float    g_attpart[32][BB][128];   // partial bias sums
__device__ double   g_acc[4];

// monotone float<->uint encoding (for atomicMax over signed floats)
__device__ __forceinline__ unsigned fenc(float f){
    unsigned u = __float_as_uint(f);
    return (u & 0x80000000u) ? ~u : (u | 0x80000000u);
}
__device__ __forceinline__ float fdec(unsigned e){
    unsigned u = (e & 0x80000000u) ? (e & 0x7fffffffu) : ~e;
    return __uint_as_float(u);
}

// ---------------- init ----------------
__global__ void k_init(const float* __restrict__ points){
    int i = blockIdx.x*blockDim.x + threadIdx.x;
    if(i < BB*NP0*3){
        int b = i/(NP0*3); int r = i - b*(NP0*3);
        g_canvas[b][r/3][r%3] = points[i];
    }
    if(i < BB*HD){ g_h[i/HD][i%HD] = 0.f; g_c[i/HD][i%HD] = 0.f; }
    if(i < 4) g_acc[i] = 0.0;
}

// ---------------- encoder layers 1-2 (per point), fused gfeat re-init ----------------
__global__ void k_enc12(const float* __restrict__ w1, const float* __restrict__ b1,
                        const float* __restrict__ w2, const float* __restrict__ b2, int N){
    __shared__ float s_w1[192];
    __shared__ float s_b1[64];
    __shared__ float s_w2[64*128];
    __shared__ float s_b2[128];
    int tid = threadIdx.x;
    if(blockIdx.x == 0){  // re-init gfeat max accumulators for this step
        for(int i=tid;i<BB*GD;i+=256) ((unsigned*)g_gfenc)[i] = fenc(-FLT_MAX);
    }
    for(int i=tid;i<192;i+=256) s_w1[i]=w1[i];
    if(tid<64)  s_b1[tid]=b1[tid];
    if(tid<128) s_b2[tid]=b2[tid];
    for(int i=tid;i<8192;i+=256) s_w2[i]=w2[i];
    __syncthreads();

    int p = blockIdx.x*256 + tid;
    if(p >= BB*N) return;
    int b = p / N, n = p - b*N;
    float x = g_canvas[b][n][0], y = g_canvas[b][n][1], z = g_canvas[b][n][2];

    float f1[64];
    #pragma unroll
    for(int o=0;o<64;o++)
        f1[o] = fmaxf(0.f, s_b1[o] + x*s_w1[o] + y*s_w1[64+o] + z*s_w1[128+o]);

    size_t col = (size_t)b*MAXN + n;
    for(int j=0;j<128;j+=4){
        float a0=s_b2[j], a1=s_b2[j+1], a2=s_b2[j+2], a3=s_b2[j+3];
        #pragma unroll
        for(int k=0;k<64;k++){
            float4 w = *(const float4*)&s_w2[k*128 + j];
            float f = f1[k];
            a0 += f*w.x; a1 += f*w.y; a2 += f*w.z; a3 += f*w.w;
        }
        g_F2T[j  ][col] = fmaxf(a0,0.f);
        g_F2T[j+1][col] = fmaxf(a1,0.f);
        g_F2T[j+2][col] = fmaxf(a2,0.f);
        g_F2T[j+3][col] = fmaxf(a3,0.f);
    }
}

// ---------------- encoder layer 3 GEMM + channel max (gfeat) ----------------
// grid (BB, N/64), block 256.  Tile: 64 points x 256 channels.
// K=128 staged through smem in 4 chunks of 32 -> inner loop is pure LDS+FFMA.
__global__ void __launch_bounds__(256,2)
k_enc3(const float* __restrict__ w3, const float* __restrict__ b3){
    __shared__ float sW[32*256];   // [kk][ch]  32KB
    __shared__ float sF[32*64];    // [kk][p]    8KB  (reused as reduce buf)
    int b = blockIdx.x;
    int pbase = blockIdx.y*64;
    int tid = threadIdx.x;
    int lane = tid & 31, pg = tid >> 5;
    int c0 = lane*4, c1 = 128 + lane*4;
    size_t base = (size_t)b*MAXN + pbase;

    float acc[8][8];
    #pragma unroll
    for(int i=0;i<8;i++)
        #pragma unroll
        for(int j=0;j<8;j++) acc[i][j]=0.f;

    for(int kc=0;kc<128;kc+=32){
        __syncthreads();
        {   // stage w3 chunk: rows kc..kc+31 (contiguous 8192 floats)
            const float4* wsrc = (const float4*)(w3 + (size_t)kc*256);
            float4* wdst = (float4*)sW;
            #pragma unroll
            for(int i=0;i<8;i++) wdst[tid + i*256] = wsrc[tid + i*256];
        }
        {   // stage F2T chunk: 32 rows x 64 points
            #pragma unroll
            for(int i=0;i<8;i++){
                int idx = tid + i*256;
                int k = idx>>6, p = idx&63;
                sF[idx] = g_F2T[kc+k][base+p];
            }
        }
        __syncthreads();
        #pragma unroll 4
        for(int k=0;k<32;k++){
            float4 wa = *(const float4*)&sW[k*256 + c0];
            float4 wb = *(const float4*)&sW[k*256 + c1];
            float4 fa = *(const float4*)&sF[k*64 + pg*8];
            float4 fb = *(const float4*)&sF[k*64 + pg*8 + 4];
            float f[8] = {fa.x,fa.y,fa.z,fa.w,fb.x,fb.y,fb.z,fb.w};
            float w[8] = {wa.x,wa.y,wa.z,wa.w,wb.x,wb.y,wb.z,wb.w};
            #pragma unroll
            for(int i=0;i<8;i++)
                #pragma unroll
                for(int j=0;j<8;j++)
                    acc[i][j] += f[i]*w[j];
        }
    }
    // per-thread max over 8 points; +bias (max(a)+b == max(a+b))
    float m[8];
    #pragma unroll
    for(int j=0;j<8;j++){
        float mm = acc[0][j];
        #pragma unroll
        for(int i=1;i<8;i++) mm = fmaxf(mm, acc[i][j]);
        int ch = (j<4) ? (c0+j) : (c1+j-4);
        m[j] = mm + b3[ch];
    }
    __syncthreads();
    #pragma unroll
    for(int j=0;j<8;j++){
        int ch = (j<4) ? (c0+j) : (c1+j-4);
        sF[pg*256 + ch] = m[j];
    }
    __syncthreads();
    {
        int ch = tid;   // 256 channels
        float mm = sF[ch];
        #pragma unroll
        for(int g=1;g<8;g++) mm = fmaxf(mm, sF[g*256 + ch]);
        atomicMax(&g_gfenc[b][ch], fenc(mm));
    }
}

// ---------------- attention bias partials: grid (BB, 32), 128 threads ----------------
__global__ void k_attpre(const float* __restrict__ att_w1, const float* __restrict__ att_b1){
    int b = blockIdx.x, s = blockIdx.y;
    int j = threadIdx.x;
    int r0 = s*12;
    float acc = (s==0) ? att_b1[j] : 0.f;
    #pragma unroll
    for(int kk=0;kk<12;kk++){
        int r = r0 + kk;              // 0..383
        float v = (r < GD) ? fdec(g_gfenc[b][r]) : g_h[b][r-GD];
        acc += v * att_w1[(3+r)*128 + j];
    }
    g_attpart[s][b][j] = acc;
}

// ---------------- attention score per point ----------------
__global__ void k_attscore(const float* __restrict__ att_w1, const float* __restrict__ att_w2,
                           const float* __restrict__ att_b2, int N){
    __shared__ float  s_ab[128];
    __shared__ float4 s_pk[128];       // {w1x,w1y,w1z,w2} per hidden unit
    int b = blockIdx.y;
    int tid = threadIdx.x;
    if(tid < 128){
        float a = 0.f;
        #pragma unroll
        for(int s=0;s<32;s++) a += g_attpart[s][b][tid];
        s_ab[tid] = a;
        s_pk[tid] = make_float4(att_w1[tid], att_w1[128+tid], att_w1[256+tid], att_w2[tid]);
    }
    __syncthreads();

    int n = blockIdx.x*256 + tid;
    if(n >= N) return;
    float x = g_canvas[b][n][0], y = g_canvas[b][n][1], z = g_canvas[b][n][2];
    float s = att_b2[0];
    #pragma unroll 4
    for(int jj=0;jj<128;jj++){
        float4 w = s_pk[jj];
        float hv = s_ab[jj] + x*w.x + y*w.y + z*w.z;
        s += fmaxf(hv, 0.f) * w.w;
    }
    g_scores[b][n] = s;
}

// ---------------- fused softmax + center + top-K + LSTM + ref1 ----------------
// one block per batch, 1024 threads, dynamic smem = MAXN*4 bytes for d2
__global__ void __launch_bounds__(1024)
k_center(int N,
         const float* __restrict__ wih, const float* __restrict__ whh,
         const float* __restrict__ bih, const float* __restrict__ bhh,
         const float* __restrict__ ref_w1, const float* __restrict__ ref_b1){
    extern __shared__ float sD[];
    __shared__ float rw[32];
    __shared__ int   ri[32];
    __shared__ float s4[32][4];
    __shared__ float s_bc[8];
    __shared__ int   s_itot;
    __shared__ unsigned s_eqn;
    __shared__ int   s_eqi[256];
    __shared__ float s_in[262];
    __shared__ float s_g[512];
    __shared__ float s_hold[HD];
    __shared__ float s_hn[HD];
    int b = blockIdx.x, tid = threadIdx.x;
    int lane = tid & 31, wid = tid >> 5;

    // --- max of scores ---
    float m = -FLT_MAX;
    for(int n=tid;n<N;n+=1024) m = fmaxf(m, g_scores[b][n]);
    #pragma unroll
    for(int o=16;o;o>>=1) m = fmaxf(m, __shfl_xor_sync(0xffffffffu, m, o));
    if(lane==0) rw[wid] = m;
    __syncthreads();
    if(tid==0){
        float mm = rw[0];
        for(int i=1;i<32;i++) mm = fmaxf(mm, rw[i]);
        s_bc[0] = mm;
    }
    __syncthreads();
    float mx = s_bc[0];

    // --- exp sums + weighted coordinate sums ---
    float se=0,sx=0,sy=0,sz=0;
    for(int n=tid;n<N;n+=1024){
        float e = expf(g_scores[b][n]-mx);
        se += e;
        sx += e*g_canvas[b][n][0];
        sy += e*g_canvas[b][n][1];
        sz += e*g_canvas[b][n][2];
    }
    #pragma unroll
    for(int o=16;o;o>>=1){
        se += __shfl_xor_sync(0xffffffffu, se, o);
        sx += __shfl_xor_sync(0xffffffffu, sx, o);
        sy += __shfl_xor_sync(0xffffffffu, sy, o);
        sz += __shfl_xor_sync(0xffffffffu, sz, o);
    }
    if(lane==0){ s4[wid][0]=se; s4[wid][1]=sx; s4[wid][2]=sy; s4[wid][3]=sz; }
    __syncthreads();
    if(tid==0){
        float te=0,tx=0,ty=0,tz=0;
        for(int i=0;i<32;i++){ te+=s4[i][0]; tx+=s4[i][1]; ty+=s4[i][2]; tz+=s4[i][3]; }
        float cx=tx/te, cy=ty/te, cz=tz/te;
        s_bc[1]=cx; s_bc[2]=cy; s_bc[3]=cz;
        g_center[b][0]=cx; g_center[b][1]=cy; g_center[b][2]=cz;
        s_eqn = 0;
    }
    __syncthreads();
    float cx=s_bc[1], cy=s_bc[2], cz=s_bc[3];

    // --- squared distances into smem (monotone with dist -> same top-K) ---
    for(int n=tid;n<N;n+=1024){
        float dx=g_canvas[b][n][0]-cx, dy=g_canvas[b][n][1]-cy, dz=g_canvas[b][n][2]-cz;
        sD[n] = dx*dx+dy*dy+dz*dz;
    }
    __syncthreads();

    // --- binary search on (nonneg) float bits for K-th smallest ---
    unsigned lo=0u, hi=0x7f800000u;
    while(lo < hi){
        unsigned mid = lo + ((hi-lo)>>1);
        int c=0;
        for(int n=tid;n<N;n+=1024) c += (__float_as_uint(sD[n]) <= mid);
        #pragma unroll
        for(int o=16;o;o>>=1) c += __shfl_xor_sync(0xffffffffu, c, o);
        if(lane==0) ri[wid]=c;
        __syncthreads();
        if(tid==0){ int t=0; for(int i=0;i<32;i++) t+=ri[i]; s_itot=t; }
        __syncthreads();
        if(s_itot >= KSEL) hi = mid; else lo = mid+1;
    }
    unsigned u = lo;

    // --- sums of strictly-below + boundary ties (index order matches lax.top_k) ---
    float ax=0,ay=0,az=0; int c=0;
    for(int n=tid;n<N;n+=1024){
        unsigned bits = __float_as_uint(sD[n]);
        if(bits < u){
            c++; ax+=g_canvas[b][n][0]; ay+=g_canvas[b][n][1]; az+=g_canvas[b][n][2];
        }
        if(bits == u){
            unsigned p = atomicAdd(&s_eqn, 1u);
            if(p < 256) s_eqi[p] = n;
        }
    }
    #pragma unroll
    for(int o=16;o;o>>=1){
        c  += __shfl_xor_sync(0xffffffffu, c, o);
        ax += __shfl_xor_sync(0xffffffffu, ax, o);
        ay += __shfl_xor_sync(0xffffffffu, ay, o);
        az += __shfl_xor_sync(0xffffffffu, az, o);
    }
    if(lane==0){ ri[wid]=c; s4[wid][0]=ax; s4[wid][1]=ay; s4[wid][2]=az; }
    __syncthreads();
    if(tid==0){
        int tc=0; float tx=0,ty=0,tz=0;
        for(int i=0;i<32;i++){ tc+=ri[i]; tx+=s4[i][0]; ty+=s4[i][1]; tz+=s4[i][2]; }
        int r = KSEL - tc;                 // boundary elems needed, in index order
        int mcount = min((int)s_eqn, 256);
        for(int it=0; it<r; it++){
            int best=-1, bi=0x7fffffff;
            for(int q=0;q<mcount;q++){ int v=s_eqi[q]; if(v>=0 && v<bi){bi=v;best=q;} }
            if(best<0) break;
            s_eqi[best] = -1;
            tx += g_canvas[b][bi][0]; ty += g_canvas[b][bi][1]; tz += g_canvas[b][bi][2];
        }
        float inv = 1.f/KSEL;
        float px = tx*inv - cx, py = ty*inv - cy, pz = tz*inv - cz;
        g_patch[b][0]=px; g_patch[b][1]=py; g_patch[b][2]=pz;
        s_bc[4]=px; s_bc[5]=py; s_bc[6]=pz;
    }
    __syncthreads();

    // ===== fused LSTM gates + cell + refine layer 1 (this batch only) =====
    for(int i=tid;i<262;i+=1024){
        float v;
        if(i < GD)        v = fdec(g_gfenc[b][i]);
        else if(i < GD+3) v = s_bc[1+i-GD];
        else              v = s_bc[4+i-GD-3];
        s_in[i]=v;
    }
    for(int i=tid;i<HD;i+=1024) s_hold[i]=g_h[b][i];
    __syncthreads();
    if(tid < 512){   // gate j for this batch (same per-(b,j) accumulation order as before)
        int j = tid;
        float a = bih[j] + bhh[j];
        #pragma unroll 2
        for(int k=0;k<262;k++) a += s_in[k]*wih[k*512 + j];
        #pragma unroll 2
        for(int k=0;k<HD;k++)  a += s_hold[k]*whh[k*512 + j];
        s_g[j]=a;
    }
    __syncthreads();
    if(tid < HD){
        int j = tid;
        float gi=s_g[j], gf=s_g[HD+j], gg=s_g[2*HD+j], go=s_g[3*HD+j];
        float sgi=1.f/(1.f+expf(-gi)), sgf=1.f/(1.f+expf(-gf)), sgo=1.f/(1.f+expf(-go));
        float cc = sgf*g_c[b][j] + sgi*tanhf(gg);
        g_c[b][j] = cc;
        float h = sgo*tanhf(cc);
        g_h[b][j] = h;
        s_hn[j] = h;
    }
    __syncthreads();
    if(tid < HD){
        int j = tid;
        float a = ref_b1[j];
        #pragma unroll 2
        for(int k=0;k<HD;k++) a += s_hn[k]*ref_w1[k*128+j];
        g_hid[b][j] = fmaxf(a, 0.f);
    }
}

// ---------------- refine decoder layer 2 -> new canvas points ----------------
__global__ void k_ref2(const float* __restrict__ ref_w2, const float* __restrict__ ref_b2, int N){
    int o = blockIdx.x*256 + threadIdx.x;
    if(o >= BB*REFO) return;
    int b = o/REFO, q = o - b*REFO;
    float a = ref_b2[q];
    const float* h = g_hid[b];
    #pragma unroll 4
    for(int k=0;k<HD;k++) a += h[k]*ref_w2[k*REFO + q];
    int pt = q/3, d = q - 3*pt;
    g_canvas[b][N+pt][d] = a*0.02f + g_center[b][d];
}

// ---------------- chamfer: all 4 directions in one launch ----------------
// dir0: min over gt of canvas[0:4096)          -> acc0   (16 tiles)
// dir1: min over canvas[0:4096) of gt          -> acc1   (16 tiles)
// dir2: min over gt of canvas[4096:15616)      -> acc2   (45 tiles)
// dir3: min over canvas[4096:15616) of gt      -> acc3   (16 tiles)
#define CTI 2048
__global__ void k_cham(const float* __restrict__ gt){
    __shared__ float4 sy[CTI];
    __shared__ float red[256];
    int b = blockIdx.y, tid = threadIdx.x;
    int t = blockIdx.x;
    int dir, tb;
    if(t < 16){ dir=0; tb=t; }
    else if(t < 32){ dir=1; tb=t-16; }
    else if(t < 77){ dir=2; tb=t-32; }
    else { dir=3; tb=t-77; }

    int xsel = (dir==1 || dir==3) ? 1 : 0;           // 0=canvas, 1=gt
    int xoff = (dir==2) ? NP0 : 0;
    int ysel = 1 - xsel;
    int yoff = (dir==3) ? NP0 : 0;
    int Ny   = (dir==3) ? (MAXN-NP0) : NP0;
    int ai   = dir;

    int n = tb*256 + tid;   // all tiles are full (4096 and 11520 divisible by 256)
    float x0,x1,x2;
    if(xsel==0){
        x0=g_canvas[b][xoff+n][0]; x1=g_canvas[b][xoff+n][1]; x2=g_canvas[b][xoff+n][2];
    } else {
        const float* p = gt + ((size_t)b*NP0 + n)*3;
        x0=p[0]; x1=p[1]; x2=p[2];
    }
    float xx = x0*x0 + x1*x1 + x2*x2;
    float mn0=FLT_MAX, mn1=FLT_MAX, mn2=FLT_MAX, mn3=FLT_MAX;

    for(int t0=0;t0<Ny;t0+=CTI){
        int cnt = min(CTI, Ny-t0);
        __syncthreads();
        if(ysel==0){
            for(int i=tid;i<cnt;i+=256){
                float y0=g_canvas[b][yoff+t0+i][0], y1=g_canvas[b][yoff+t0+i][1], y2=g_canvas[b][yoff+t0+i][2];
                sy[i] = make_float4(y0,y1,y2, y0*y0+y1*y1+y2*y2);
            }
        } else {
            const float* ys = gt + ((size_t)b*NP0 + t0)*3;
            for(int i=tid;i<cnt;i+=256){
                float y0=ys[3*i], y1=ys[3*i+1], y2=ys[3*i+2];
                sy[i] = make_float4(y0,y1,y2, y0*y0+y1*y1+y2*y2);
            }
        }
        __syncthreads();
        // cnt is always a multiple of 4 (2048 or 1280)
        for(int j=0;j<cnt;j+=4){
            float4 A=sy[j], B=sy[j+1], C=sy[j+2], D=sy[j+3];
            float v0 = fmaf(-2.f, fmaf(x0,A.x, fmaf(x1,A.y, x2*A.z)), A.w);
            float v1 = fmaf(-2.f, fmaf(x0,B.x, fmaf(x1,B.y, x2*B.z)), B.w);
            float v2 = fmaf(-2.f, fmaf(x0,C.x, fmaf(x1,C.y, x2*C.z)), C.w);
            float v3 = fmaf(-2.f, fmaf(x0,D.x, fmaf(x1,D.y, x2*D.z)), D.w);
            mn0 = fminf(mn0, v0);
            mn1 = fminf(mn1, v1);
            mn2 = fminf(mn2, v2);
            mn3 = fminf(mn3, v3);
        }
    }
    float mn = fminf(fminf(mn0,mn1), fminf(mn2,mn3));
    red[tid] = xx + mn;
    __syncthreads();
    for(int s=128;s>0;s>>=1){ if(tid<s) red[tid]+=red[tid+s]; __syncthreads(); }
    if(tid==0) atomicAdd(&g_acc[ai], (double)red[0]);
}

__global__ void k_final(float* __restrict__ out){
    double cd_in  = g_acc[0]/(4.0*NP0)          + g_acc[1]/(4.0*NP0);
    double cd_new = g_acc[2]/(4.0*(10.0*NEWP))  + g_acc[3]/(4.0*NP0);
    out[0] = (float)(0.1*cd_in + 1.0*cd_new);
}

// ---------------- host launch ----------------
extern "C" void kernel_launch(void* const* d_in, const int* in_sizes, int n_in,
                              void* d_out, int out_size){
    const float* points   = (const float*)d_in[0];
    const float* gt       = (const float*)d_in[1];
    const float* enc_w1   = (const float*)d_in[2];
    const float* enc_b1   = (const float*)d_in[3];
    const float* enc_w2   = (const float*)d_in[4];
    const float* enc_b2   = (const float*)d_in[5];
    const float* enc_w3   = (const float*)d_in[6];
    const float* enc_b3   = (const float*)d_in[7];
    const float* att_w1   = (const float*)d_in[8];
    const float* att_b1   = (const float*)d_in[9];
    const float* att_w2   = (const float*)d_in[10];
    const float* att_b2   = (const float*)d_in[11];
    const float* lstm_wih = (const float*)d_in[12];
    const float* lstm_whh = (const float*)d_in[13];
    const float* lstm_bih = (const float*)d_in[14];
    const float* lstm_bhh = (const float*)d_in[15];
    const float* ref_w1   = (const float*)d_in[16];
    const float* ref_b1   = (const float*)d_in[17];
    const float* ref_w2   = (const float*)d_in[18];
    const float* ref_b2   = (const float*)d_in[19];

    // opt-in dynamic smem for k_center (d2 array ~62KB); idempotent, capture-safe
    cudaFuncSetAttribute(k_center, cudaFuncAttributeMaxDynamicSharedMemorySize, 64*1024);

    k_init<<<(BB*NP0*3 + 255)/256, 256>>>(points);

    int N = NP0;
    for(int s=0;s<NSTEPS;s++){
        int P = BB*N;
        k_enc12<<<(P+255)/256, 256>>>(enc_w1, enc_b1, enc_w2, enc_b2, N);
        dim3 g3(BB, N/64);
        k_enc3<<<g3, 256>>>(enc_w3, enc_b3);
        k_attpre<<<dim3(BB,32), 128>>>(att_w1, att_b1);
        k_attscore<<<dim3((N+255)/256, BB), 256>>>(att_w1, att_w2, att_b2, N);
        k_center<<<BB, 1024, MAXN*4>>>(N, lstm_wih, lstm_whh, lstm_bih, lstm_bhh, ref_w1, ref_b1);
        k_ref2<<<(BB*REFO+255)/256, 256>>>(ref_w2, ref_b2, N);
        N += NEWP;
    }

    k_cham<<<dim3(93, BB), 256>>>(gt);
    k_final<<<1,1>>>((float*)d_out);
}